// round 11
// baseline (speedup 1.0000x reference)
#include <cuda_runtime.h>
#include <math.h>

#define T_LEN    8192
#define NDELAY   360
#define NTHREADS 1024
#define ELEMS    (T_LEN / NTHREADS)   // 8
#define PAD      1280                 // > 3*420 = 1260 max FIR lag
#define FULLMASK 0xffffffffu

// ---------------------------------------------------------------------------
// y_t = x_t - a1*y_{t-L1} - a2*y_{t-L2}  (exactly two taps: straight-through
// one-hot is exactly hard in fp32). Transfer fn 1/(1+s), s = a1 z^-L1 + a2 z^-L2.
// EVIDENCE (R5 vs R7 bit-identical rel_err=1.0859e-07): the truncated FIR
// (1-s)(1+s^2) already matches the reference to 1e-7 => rho=|a1|+|a2| is tiny.
// So compute y = (1 - s + s^2 - s^3) x  -- a 10-tap FIR, fully parallel:
//   truncation error <= rho^4/(1-rho), runtime-verified < 1e-4 (tol 1e-3).
// Stage x into front-zero-padded smem (no tap guards), one barrier, then each
// output is 10 LDS + 9 FFMA, independent across all 8192 elements.
// Serial barrier fallback retained for the (never-observed) large-rho case.
// ---------------------------------------------------------------------------

__device__ __forceinline__ float tanh_fast(float x) {
    x = fminf(fmaxf(x, -15.0f), 15.0f);
    float e = __expf(2.0f * x);
    return (e - 1.0f) * __frcp_rn(e + 1.0f);
}

__global__ void __launch_bounds__(NTHREADS, 1)
ks_fused_kernel(const float* __restrict__ x,
                const float* __restrict__ gumbel,
                const float* __restrict__ delayp,
                const float* __restrict__ fb,
                const float* __restrict__ rc,
                float* __restrict__ out) {
    extern __shared__ float buf[];      // [PAD + T_LEN]; x at +PAD
    float* X = buf + PAD;

    __shared__ float s_rv[32];
    __shared__ int   s_ri[32];
    __shared__ int   s_m;

    const int tid  = threadIdx.x;
    const int row  = blockIdx.x;
    const int lane = tid & 31;
    const int wid  = tid >> 5;
    const float* xr = x + (size_t)row * T_LEN;
    float*       yr = out + (size_t)row * T_LEN;

    // --- stage x (coalesced float4) + zero the front pad ---
    {
        const float4* x4 = (const float4*)xr;
        float4* s4 = (float4*)X;
#pragma unroll
        for (int i = 0; i < T_LEN / 4 / NTHREADS; i++)
            s4[tid + i * NTHREADS] = x4[tid + i * NTHREADS];
        buf[tid] = 0.0f;                       // pad [0,1024)
        if (tid < PAD - NTHREADS) buf[NTHREADS + tid] = 0.0f;  // pad [1024,1280)
    }

    // --- argmax over 360 logits (first-index tie-break) ---
    float lv = -INFINITY;
    int   li = tid;
    if (tid < NDELAY) lv = delayp[tid] + gumbel[tid];
#pragma unroll
    for (int off = 16; off > 0; off >>= 1) {
        float ov = __shfl_down_sync(FULLMASK, lv, off);
        int   oi = __shfl_down_sync(FULLMASK, li, off);
        if (ov > lv || (ov == lv && oi < li)) { lv = ov; li = oi; }
    }
    if (lane == 0) { s_rv[wid] = lv; s_ri[wid] = li; }

    // --- scalar coefficients (redundant per thread; fast intrinsics) ---
    float k1 = tanh_fast(tanh_fast(rc[0]));
    float k2 = tanh_fast(tanh_fast(rc[1]));
    float a1 = k1 * (1.0f - k2);
    float a2 = fminf(fmaxf(k2, -0.999f), 0.999f);
    float bound = 0.999f - fabsf(a2);
    a1 = fminf(fmaxf(a1, -bound), bound);
    float sg = __frcp_rn(1.0f + __expf(-fb[0]));
    float g  = __powf(sg, 0.45f);
    a1 *= g;
    a2 *= g;

    __syncthreads();
    if (tid < 32) {
        lv = s_rv[lane];
        li = s_ri[lane];
#pragma unroll
        for (int off = 16; off > 0; off >>= 1) {
            float ov = __shfl_down_sync(FULLMASK, lv, off);
            int   oi = __shfl_down_sync(FULLMASK, li, off);
            if (ov > lv || (ov == lv && oi < li)) { lv = ov; li = oi; }
        }
        if (lane == 0) s_m = li;
    }
    __syncthreads();   // staging + pad + argmax complete

    const int m  = s_m;
    const int L1 = 61 + m;
    const int L2 = 61 + ((m + 1) % NDELAY);

    const float rho  = fabsf(a1) + fabsf(a2);
    const float rho2 = rho * rho;
    const float rho4 = rho2 * rho2;

    if (rho4 < 1e-4f * (1.0f - rho)) {
        // ---- truncated FIR:  y = (1 - s + s^2 - s^3) x ----
        const float c1 = -a1,            c2 = -a2;
        const float c3 = a1 * a1,        c4 = 2.0f * a1 * a2,  c5 = a2 * a2;
        const float c6 = -c3 * a1,       c7 = -3.0f * c3 * a2;
        const float c8 = -3.0f * a1 * c5, c9 = -c5 * a2;
        const int   g1 = L1,          g2 = L2;
        const int   g3 = 2 * L1,      g4 = L1 + L2,      g5 = 2 * L2;
        const int   g6 = 3 * L1,      g7 = 2 * L1 + L2;
        const int   g8 = L1 + 2 * L2, g9 = 3 * L2;

#pragma unroll
        for (int i = 0; i < ELEMS; i++) {
            const int t = i * NTHREADS + tid;
            // batch the 10 independent loads (front pad makes them guard-free)
            float v0 = X[t];
            float v1 = X[t - g1];
            float v2 = X[t - g2];
            float v3 = X[t - g3];
            float v4 = X[t - g4];
            float v5 = X[t - g5];
            float v6 = X[t - g6];
            float v7 = X[t - g7];
            float v8 = X[t - g8];
            float v9 = X[t - g9];
            float acc = fmaf(c1, v1, v0);
            acc = fmaf(c2, v2, acc);
            acc = fmaf(c3, v3, acc);
            acc = fmaf(c4, v4, acc);
            acc = fmaf(c5, v5, acc);
            acc = fmaf(c6, v6, acc);
            acc = fmaf(c7, v7, acc);
            acc = fmaf(c8, v8, acc);
            acc = fmaf(c9, v9, acc);
            yr[t] = acc;
        }
        return;
    }

    // ---- fallback (large rho; not observed): serial barrier rounds ----
    {
        const int C = (L1 < L2) ? L1 : L2;
        for (int t = tid; t < C; t += NTHREADS) yr[t] = X[t];
        for (int s0 = C; s0 < T_LEN; s0 += C) {
            __syncthreads();
            const int end = (s0 + C < T_LEN) ? (s0 + C) : T_LEN;
            for (int t = s0 + tid; t < end; t += NTHREADS) {
                float v1 = (t >= L1) ? X[t - L1] : 0.0f;
                float v2 = (t >= L2) ? X[t - L2] : 0.0f;
                float y = X[t] - a1 * v1 - a2 * v2;
                X[t] = y;
                yr[t] = y;
            }
        }
    }
}

// ---------------------------------------------------------------------------
// inputs: excitation[128*8192] f32, gumbel[360], delay_param[360],
//         feedback_gain[1], reflection_coeffs[2]; output f32 [128*8192]
// ---------------------------------------------------------------------------
extern "C" void kernel_launch(void* const* d_in, const int* in_sizes, int n_in,
                              void* d_out, int out_size) {
    const float* x      = (const float*)d_in[0];
    const float* gumbel = (const float*)d_in[1];
    const float* delayp = (const float*)d_in[2];
    const float* fb     = (const float*)d_in[3];
    const float* rc     = (const float*)d_in[4];
    float* out = (float*)d_out;

    const int rows = in_sizes[0] / T_LEN;
    const int smem_bytes = (PAD + T_LEN) * sizeof(float);

    cudaFuncSetAttribute(ks_fused_kernel,
                         cudaFuncAttributeMaxDynamicSharedMemorySize, smem_bytes);
    ks_fused_kernel<<<rows, NTHREADS, smem_bytes>>>(x, gumbel, delayp, fb, rc, out);
}

// round 12
// speedup vs baseline: 1.1940x; 1.1940x over previous
#include <cuda_runtime.h>
#include <math.h>

#define T_LEN    8192
#define NDELAY   360
#define NTHREADS 1024
#define FULLMASK 0xffffffffu

// smem layout (floats): X | B | A2 | Y, each front-padded (zeroed) + tail pad
#define FPX 448
#define FPB 864
#define FPA 1696
#define FPY 32
#define TAIL 1024
#define OX 0
#define OB (OX + FPX + T_LEN + TAIL)
#define OA (OB + FPB + T_LEN + TAIL)
#define OY (OA + FPA + T_LEN + TAIL)
#define SMEM_FLOATS (OY + FPY + T_LEN + TAIL)

// ---------------------------------------------------------------------------
// y_t = x_t - a1*y_{t-L1} - a2*y_{t-L2}; exactly two taps (straight-through
// one-hot exactly hard in fp32). Established: L2 = L1+1 (m != 359 fallback
// kept), L1 in (128, 420], rho = |a1|+|a2| in [0.17, 0.87].
// Squaring ladder K passes -> serial remainder y += s^{2^K} y with taps at
// CONSECUTIVE lags W..W+NT-1, W = 2^K*L1, NT = 2^K+1 (K=0: 2 taps at L1,L1+1).
// Serial engine: thread p <-> slot p (W <= 1024). tap0 = own register from
// previous round; taps k = shfl_up(k); lane<k boundary reads Y (written >=1
// round earlier, zero front pad for t<0). No LDS on the critical path.
// Uniform cost model picks K (incl. full truncation when rho^{2^K} < 1e-5).
// ---------------------------------------------------------------------------

__device__ __forceinline__ float tanh_fast(float x) {
    x = fminf(fmaxf(x, -15.0f), 15.0f);
    float e = __expf(2.0f * x);
    return (e - 1.0f) * __frcp_rn(e + 1.0f);
}

template <int NT>
__device__ __forceinline__ void serial_run(const float* __restrict__ Xw,
                                           float* __restrict__ Y,
                                           const float* c, int W) {
    const int p    = threadIdx.x;
    const int lane = p & 31;

    // round 0: y = w on [0, W) (all lags >= W); strays beyond W are harmless
    float yp = Xw[p];
    Y[p] = yp;
    __syncthreads();

    const int nr = (T_LEN + W - 1) / W;
    int s0 = W;
    for (int r = 1; r < nr; r++) {
        float cx = Xw[s0 + p];            // read-only pass output (tail-padded)
        float u[NT - 1];
#pragma unroll
        for (int k = 1; k < NT; k++) {
            u[k - 1] = __shfl_up_sync(FULLMASK, yp, k);
            if (lane < k) u[k - 1] = Y[s0 - W + p - k];  // predicated LDS
        }
        float acc = fmaf(c[0], yp, cx);
#pragma unroll
        for (int k = 1; k < NT; k++) acc = fmaf(c[k], u[k - 1], acc);
        Y[s0 + p] = acc;                  // strays overwritten next round
        __syncthreads();
        yp = acc;
        s0 += W;
    }
}

__global__ void __launch_bounds__(NTHREADS, 1)
ks_fused_kernel(const float* __restrict__ x,
                const float* __restrict__ gumbel,
                const float* __restrict__ delayp,
                const float* __restrict__ fb,
                const float* __restrict__ rc,
                float* __restrict__ out) {
    extern __shared__ float sm[];
    float* Xd = sm + OX + FPX;
    float* Bd = sm + OB + FPB;
    float* Ad = sm + OA + FPA;
    float* Yd = sm + OY + FPY;

    __shared__ float s_rv[32];
    __shared__ int   s_ri[32];
    __shared__ int   s_m;

    const int tid  = threadIdx.x;
    const int row  = blockIdx.x;
    const int lane = tid & 31;
    const int wid  = tid >> 5;
    const float* xr = x + (size_t)row * T_LEN;
    float*       yr = out + (size_t)row * T_LEN;

    // --- stage x (coalesced float4, LDG latency hidden under setup) ---
    {
        const float4* x4 = (const float4*)xr;
        float4* s4 = (float4*)Xd;
#pragma unroll
        for (int i = 0; i < 2; i++) s4[tid + i * NTHREADS] = x4[tid + i * NTHREADS];
    }

    // --- zero the front pads ---
    if (tid < FPX) sm[OX + tid] = 0.0f;
    if (tid < FPB) sm[OB + tid] = 0.0f;
    for (int i = tid; i < FPA; i += NTHREADS) sm[OA + i] = 0.0f;
    if (tid < FPY) sm[OY + tid] = 0.0f;

    // --- argmax over 360 logits (first-index tie-break) ---
    float lv = -INFINITY;
    int   li = tid;
    if (tid < NDELAY) lv = delayp[tid] + gumbel[tid];
#pragma unroll
    for (int off = 16; off > 0; off >>= 1) {
        float ov = __shfl_down_sync(FULLMASK, lv, off);
        int   oi = __shfl_down_sync(FULLMASK, li, off);
        if (ov > lv || (ov == lv && oi < li)) { lv = ov; li = oi; }
    }
    if (lane == 0) { s_rv[wid] = lv; s_ri[wid] = li; }

    // --- scalar coefficients (redundant per thread, deterministic) ---
    float k1 = tanh_fast(tanh_fast(rc[0]));
    float k2 = tanh_fast(tanh_fast(rc[1]));
    float a1 = k1 * (1.0f - k2);
    float a2 = fminf(fmaxf(k2, -0.999f), 0.999f);
    float bound = 0.999f - fabsf(a2);
    a1 = fminf(fmaxf(a1, -bound), bound);
    float sg = __frcp_rn(1.0f + __expf(-fb[0]));
    float g  = __powf(sg, 0.45f);
    a1 *= g;
    a2 *= g;

    __syncthreads();
    if (tid < 32) {
        lv = s_rv[lane];
        li = s_ri[lane];
#pragma unroll
        for (int off = 16; off > 0; off >>= 1) {
            float ov = __shfl_down_sync(FULLMASK, lv, off);
            int   oi = __shfl_down_sync(FULLMASK, li, off);
            if (ov > lv || (ov == lv && oi < li)) { lv = ov; li = oi; }
        }
        if (lane == 0) s_m = li;
    }
    __syncthreads();   // staging + pads + argmax complete

    const int m  = s_m;
    const int L1 = 61 + m;
    const int L2 = 61 + ((m + 1) % NDELAY);

    if (L2 != L1 + 1) {
        // --- fallback (m == 359): in-place barrier rounds on Xd, width C ---
        const int C = (L1 < L2) ? L1 : L2;
        for (int s0 = C; s0 < T_LEN; s0 += C) {
            __syncthreads();
            const int t = s0 + tid;
            if (tid < C && t < T_LEN)
                Xd[t] = Xd[t] - a1 * Xd[t - L1] - a2 * Xd[t - L2];
        }
        __syncthreads();
        float4* o4 = (float4*)yr;
        const float4* r4 = (const float4*)Xd;
#pragma unroll
        for (int i = 0; i < 2; i++) o4[tid + i * NTHREADS] = r4[tid + i * NTHREADS];
        return;
    }

    // --- uniform cost model: pick K in 0..3 ---
    const float rho  = fabsf(a1) + fabsf(a2);
    const float rp[4] = { rho, rho * rho, rho * rho * rho * rho,
                          (rho * rho * rho * rho) * (rho * rho * rho * rho) };
    const float passCum[4] = { 0.0f, 900.0f, 1900.0f, 3400.0f };
    int K = 0;
    {
        float best = 1e30f;
#pragma unroll
        for (int k = 0; k < 4; k++) {
            const int W = L1 << k;
            int rounds = (rp[k] < 1e-5f) ? 0 : (T_LEN + W - 1) / W;
            bool valid = (rounds == 0) || (W <= NTHREADS);
            float cost = passCum[k] + 110.0f * (float)rounds;
            if (valid && cost < best) { best = cost; K = k; }
        }
    }

    // --- FIR ladder with register carry ---
    const float a1_2 = a1 * a1, a2_2 = a2 * a2;
    float rcar[8];
    const float* res = Xd;     // serial input / trunc result
    if (K >= 1) {              // B = (1 - s) X
#pragma unroll
        for (int i = 0; i < 8; i++) {
            const int t = i * NTHREADS + tid;
            float w = fmaf(-a1, Xd[t - L1], Xd[t]);
            w = fmaf(-a2, Xd[t - L1 - 1], w);
            Bd[t] = w; rcar[i] = w;
        }
        __syncthreads();
        res = Bd;
    }
    if (K >= 2) {              // A2 = (1 + s^2) B
        const float q0 = a1_2, q1 = 2.0f * a1 * a2, q2 = a2_2;
        const int gl = 2 * L1;
#pragma unroll
        for (int i = 0; i < 8; i++) {
            const int t = i * NTHREADS + tid;
            float w = fmaf(q0, Bd[t - gl], rcar[i]);
            w = fmaf(q1, Bd[t - gl - 1], w);
            w = fmaf(q2, Bd[t - gl - 2], w);
            Ad[t] = w; rcar[i] = w;
        }
        __syncthreads();
        res = Ad;
    }
    if (K >= 3) {              // X = (1 + s^4) A2   (x no longer needed)
        const float q0 = a1_2 * a1_2, q1 = 4.0f * a1_2 * a1 * a2,
                    q2 = 6.0f * a1_2 * a2_2, q3 = 4.0f * a1 * a2_2 * a2,
                    q4 = a2_2 * a2_2;
        const int gl = 4 * L1;
#pragma unroll
        for (int i = 0; i < 8; i++) {
            const int t = i * NTHREADS + tid;
            float w = fmaf(q0, Ad[t - gl], rcar[i]);
            w = fmaf(q1, Ad[t - gl - 1], w);
            w = fmaf(q2, Ad[t - gl - 2], w);
            w = fmaf(q3, Ad[t - gl - 3], w);
            w = fmaf(q4, Ad[t - gl - 4], w);
            Xd[t] = w; rcar[i] = w;
        }
        __syncthreads();
        res = Xd;
    }

    // --- serial remainder (skipped when truncated) ---
    if (rp[K] >= 1e-5f) {
        const int W = L1 << K;
        if (K == 0) {
            const float c[2] = { -a1, -a2 };
            serial_run<2>(Xd, Yd, c, W);
        } else if (K == 1) {
            const float c[3] = { a1_2, 2.0f * a1 * a2, a2_2 };
            serial_run<3>(Bd, Yd, c, W);
        } else if (K == 2) {
            const float c[5] = { a1_2 * a1_2, 4.0f * a1_2 * a1 * a2,
                                 6.0f * a1_2 * a2_2, 4.0f * a1 * a2_2 * a2,
                                 a2_2 * a2_2 };
            serial_run<5>(Ad, Yd, c, W);
        } else {
            const float a1_4 = a1_2 * a1_2, a2_4 = a2_2 * a2_2;
            const float c[9] = { a1_4 * a1_4, 8.0f * a1_4 * a1_2 * a1 * a2,
                                 28.0f * a1_4 * a1_2 * a2_2,
                                 56.0f * a1_4 * a1 * a2_2 * a2,
                                 70.0f * a1_4 * a2_4,
                                 56.0f * a1_2 * a1 * a2_4 * a2,
                                 28.0f * a1_2 * a2_4 * a2_2,
                                 8.0f * a1 * a2_4 * a2_2 * a2, a2_4 * a2_4 };
            serial_run<9>(Xd, Yd, c, W);
        }
        res = Yd;
    }

    // --- vectorized writeback ---
    {
        float4* o4 = (float4*)yr;
        const float4* r4 = (const float4*)res;
#pragma unroll
        for (int i = 0; i < 2; i++) o4[tid + i * NTHREADS] = r4[tid + i * NTHREADS];
    }
}

// ---------------------------------------------------------------------------
// inputs: excitation[128*8192] f32, gumbel[360], delay_param[360],
//         feedback_gain[1], reflection_coeffs[2]; output f32 [128*8192]
// ---------------------------------------------------------------------------
extern "C" void kernel_launch(void* const* d_in, const int* in_sizes, int n_in,
                              void* d_out, int out_size) {
    const float* x      = (const float*)d_in[0];
    const float* gumbel = (const float*)d_in[1];
    const float* delayp = (const float*)d_in[2];
    const float* fb     = (const float*)d_in[3];
    const float* rc     = (const float*)d_in[4];
    float* out = (float*)d_out;

    const int rows = in_sizes[0] / T_LEN;
    const int smem_bytes = SMEM_FLOATS * sizeof(float);

    cudaFuncSetAttribute(ks_fused_kernel,
                         cudaFuncAttributeMaxDynamicSharedMemorySize, smem_bytes);
    ks_fused_kernel<<<rows, NTHREADS, smem_bytes>>>(x, gumbel, delayp, fb, rc, out);
}